// round 3
// baseline (speedup 1.0000x reference)
#include <cuda_runtime.h>
#include <cuda_bf16.h>

// ---------------------------------------------------------------------------
// QNN: batched 4-qubit circuit + Linear(4,6) + softmax.
//
// Math restructuring vs reference:
//  * state after RY(x_i) encoding is a PRODUCT state (outer product of
//    (cos(x/2), sin(x/2)) pairs) -> 24 mults instead of 4 layer applies.
//  * first weight layer folds into the encoding: RY(w)RY(x)|0> = RY(x+w)|0>
//    (rotations about the same axis add).
//  * CNOT = compile-time index permutation (register rename, 0 instructions).
//  * remaining 2 RY layers use batch-uniform (cos,sin) precomputed once.
//  * <Z_w> via butterfly partial sums (44 adds for all four expvals).
// Index convention: idx = q0*8 + q1*4 + q2*2 + q3  (qubit i at bit 3-i).
// ---------------------------------------------------------------------------

struct Params {
    float w0[4];            // layer-0 weight angles (folded into x)
    float c1[4], s1[4];     // cos/sin of 0.5*w1
    float c2[4], s2[4];     // cos/sin of 0.5*w2
    float W[6][4];          // linear weights
    float b[6];             // bias
};

__device__ Params g_params;

__global__ void prep_kernel(const float* __restrict__ qw,   // (3,4)
                            const float* __restrict__ W,    // (6,4)
                            const float* __restrict__ b)    // (6,)
{
    if (threadIdx.x == 0 && blockIdx.x == 0) {
        #pragma unroll
        for (int i = 0; i < 4; i++) g_params.w0[i] = qw[i];
        #pragma unroll
        for (int i = 0; i < 4; i++) {
            float h = 0.5f * qw[4 + i];
            g_params.c1[i] = cosf(h); g_params.s1[i] = sinf(h);
        }
        #pragma unroll
        for (int i = 0; i < 4; i++) {
            float h = 0.5f * qw[8 + i];
            g_params.c2[i] = cosf(h); g_params.s2[i] = sinf(h);
        }
        for (int j = 0; j < 6; j++) {
            for (int i = 0; i < 4; i++) g_params.W[j][i] = W[j * 4 + i];
            g_params.b[j] = b[j];
        }
    }
}

// CNOT(control, target): psi'[idx] = psi[idx ^ tgt_mask] when control bit set.
// All indices compile-time constant after unroll -> pure register renames.
__device__ __forceinline__ void apply_cnot_ring(float* __restrict__ psi)
{
    float t[16];
    // CNOT(0,1): control bit 3, target bit 2
    #pragma unroll
    for (int i = 0; i < 16; i++) t[i] = psi[((i >> 3) & 1) ? (i ^ 4) : i];
    float t2[16];
    // CNOT(1,2): control bit 2, target bit 1
    #pragma unroll
    for (int i = 0; i < 16; i++) t2[i] = t[((i >> 2) & 1) ? (i ^ 2) : i];
    // CNOT(2,3): control bit 1, target bit 0
    #pragma unroll
    for (int i = 0; i < 16; i++) t[i] = t2[((i >> 1) & 1) ? (i ^ 1) : i];
    // CNOT(3,0): control bit 0, target bit 3
    #pragma unroll
    for (int i = 0; i < 16; i++) psi[i] = t[(i & 1) ? (i ^ 8) : i];
}

__device__ __forceinline__ void apply_ry_layer(float* __restrict__ psi,
                                               const float* __restrict__ cv,
                                               const float* __restrict__ sv)
{
    #pragma unroll
    for (int q = 0; q < 4; q++) {
        const int m = 1 << (3 - q);
        const float cq = cv[q], sq = sv[q];
        #pragma unroll
        for (int i = 0; i < 16; i++) {
            if (!(i & m)) {
                float a0 = psi[i];
                float a1 = psi[i | m];
                psi[i]     = cq * a0 - sq * a1;
                psi[i | m] = sq * a0 + cq * a1;
            }
        }
    }
}

__global__ __launch_bounds__(256) void qnn_kernel(const float4* __restrict__ x,
                                                  float* __restrict__ out,
                                                  int B)
{
    __shared__ Params sp;
    __shared__ float obuf[256 * 6];

    // stage uniform params into shared (LDS broadcast thereafter)
    {
        constexpr int NW = sizeof(Params) / 4;
        if (threadIdx.x < NW)
            ((float*)&sp)[threadIdx.x] = ((const float*)&g_params)[threadIdx.x];
    }
    __syncthreads();

    const int tid = threadIdx.x;
    const int gid = blockIdx.x * 256 + tid;

    if (gid < B) {
        float4 xv = x[gid];

        // fold layer-0 weights into encoding angles; half-angle sincos
        float c[4], s[4];
        __sincosf(0.5f * (xv.x + sp.w0[0]), &s[0], &c[0]);
        __sincosf(0.5f * (xv.y + sp.w0[1]), &s[1], &c[1]);
        __sincosf(0.5f * (xv.z + sp.w0[2]), &s[2], &c[2]);
        __sincosf(0.5f * (xv.w + sp.w0[3]), &s[3], &c[3]);

        // product state: psi[b0b1b2b3] = f0(b0) f1(b1) f2(b2) f3(b3)
        float u[4], v[4];
        u[0] = c[0] * c[1]; u[1] = c[0] * s[1]; u[2] = s[0] * c[1]; u[3] = s[0] * s[1];
        v[0] = c[2] * c[3]; v[1] = c[2] * s[3]; v[2] = s[2] * c[3]; v[3] = s[2] * s[3];

        float psi[16];
        #pragma unroll
        for (int a = 0; a < 4; a++)
            #pragma unroll
            for (int bb = 0; bb < 4; bb++)
                psi[a * 4 + bb] = u[a] * v[bb];

        // remaining circuit: ring, RY(w1), ring, RY(w2)
        apply_cnot_ring(psi);
        apply_ry_layer(psi, sp.c1, sp.s1);
        apply_cnot_ring(psi);
        apply_ry_layer(psi, sp.c2, sp.s2);

        // probabilities
        float p[16];
        #pragma unroll
        for (int i = 0; i < 16; i++) p[i] = psi[i] * psi[i];

        // <Z_w> via butterfly partial sums
        float A[8], D[8];
        #pragma unroll
        for (int j = 0; j < 8; j++) {
            A[j] = p[j] + p[j + 8];
            D[j] = p[j] - p[j + 8];
        }
        float e0 = ((D[0] + D[1]) + (D[2] + D[3])) + ((D[4] + D[5]) + (D[6] + D[7]));
        float e1 = ((A[0] + A[1]) + (A[2] + A[3])) - ((A[4] + A[5]) + (A[6] + A[7]));
        float e2 = ((A[0] + A[1]) + (A[4] + A[5])) - ((A[2] + A[3]) + (A[6] + A[7]));
        float e3 = ((A[0] + A[2]) + (A[4] + A[6])) - ((A[1] + A[3]) + (A[5] + A[7]));

        // Linear(4,6) + softmax
        float ex[6];
        float den = 0.f;
        #pragma unroll
        for (int j = 0; j < 6; j++) {
            float l = sp.b[j];
            l = fmaf(e0, sp.W[j][0], l);
            l = fmaf(e1, sp.W[j][1], l);
            l = fmaf(e2, sp.W[j][2], l);
            l = fmaf(e3, sp.W[j][3], l);
            ex[j] = __expf(l);
            den += ex[j];
        }
        float inv = 1.0f / den;
        #pragma unroll
        for (int j = 0; j < 6; j++)
            obuf[tid * 6 + j] = ex[j] * inv;
    }
    __syncthreads();

    // coalesced store of the block's (256,6) output slab
    const long long base  = (long long)blockIdx.x * (256 * 6);
    const long long limit = (long long)B * 6;
    #pragma unroll
    for (int k = 0; k < 6; k++) {
        long long idx = base + k * 256 + tid;
        if (idx < limit) out[idx] = obuf[k * 256 + tid];
    }
}

extern "C" void kernel_launch(void* const* d_in, const int* in_sizes, int n_in,
                              void* d_out, int out_size)
{
    const float* x  = (const float*)d_in[0];   // (B,4)
    const float* qw = (const float*)d_in[1];   // (3,4)
    const float* W  = (const float*)d_in[2];   // (6,4)
    const float* b  = (const float*)d_in[3];   // (6,)
    float* out = (float*)d_out;                // (B,6)

    const int B = in_sizes[0] / 4;

    prep_kernel<<<1, 32>>>(qw, W, b);
    const int blocks = (B + 255) / 256;
    qnn_kernel<<<blocks, 256>>>((const float4*)x, out, B);
}

// round 7
// speedup vs baseline: 1.0227x; 1.0227x over previous
#include <cuda_runtime.h>
#include <cuda_bf16.h>

// ---------------------------------------------------------------------------
// QNN: batched 4-qubit circuit + Linear(4,6) + softmax.
// Round 7 (= Round 4 kernel, resubmitted through infra failures):
// f32x2-packed math, 2 samples per thread.
//
//  * product-state encoding + layer-0 angle folding
//  * ALL circuit FMA/MUL/ADD packed as fma.rn.f32x2 / mul.rn.f32x2 /
//    add.rn.f32x2 across the two samples (ptxas never emits FFMA2 from C++).
//  * subtraction = fma2(packed(-1), y, x)
//  * CNOT = compile-time register permutation (0 instructions)
//  * scalar tail (linear+softmax) per sample; smem-staged coalesced stores
// Index convention: idx = q0*8 + q1*4 + q2*2 + q3  (qubit i at bit 3-i).
// ---------------------------------------------------------------------------

typedef unsigned long long u64;

struct Params {
    float w0[4];            // layer-0 weight angles (folded into x)
    float c1[4], s1[4];     // cos/sin of 0.5*w1
    float c2[4], s2[4];     // cos/sin of 0.5*w2
    float W[6][4];          // linear weights
    float b[6];             // bias
};

__device__ Params g_params;

__global__ void prep_kernel(const float* __restrict__ qw,   // (3,4)
                            const float* __restrict__ W,    // (6,4)
                            const float* __restrict__ b)    // (6,)
{
    if (threadIdx.x == 0 && blockIdx.x == 0) {
        #pragma unroll
        for (int i = 0; i < 4; i++) g_params.w0[i] = qw[i];
        #pragma unroll
        for (int i = 0; i < 4; i++) {
            float h = 0.5f * qw[4 + i];
            g_params.c1[i] = cosf(h); g_params.s1[i] = sinf(h);
        }
        #pragma unroll
        for (int i = 0; i < 4; i++) {
            float h = 0.5f * qw[8 + i];
            g_params.c2[i] = cosf(h); g_params.s2[i] = sinf(h);
        }
        for (int j = 0; j < 6; j++) {
            for (int i = 0; i < 4; i++) g_params.W[j][i] = W[j * 4 + i];
            g_params.b[j] = b[j];
        }
    }
}

// ---- packed f32x2 primitives -------------------------------------------------
__device__ __forceinline__ u64 pk(float lo, float hi) {
    u64 r; asm("mov.b64 %0, {%1, %2};" : "=l"(r) : "f"(lo), "f"(hi)); return r;
}
__device__ __forceinline__ void upk(u64 v, float& lo, float& hi) {
    asm("mov.b64 {%0, %1}, %2;" : "=f"(lo), "=f"(hi) : "l"(v));
}
__device__ __forceinline__ u64 fma2(u64 a, u64 b, u64 c) {
    u64 d; asm("fma.rn.f32x2 %0, %1, %2, %3;" : "=l"(d) : "l"(a), "l"(b), "l"(c)); return d;
}
__device__ __forceinline__ u64 mul2(u64 a, u64 b) {
    u64 d; asm("mul.rn.f32x2 %0, %1, %2;" : "=l"(d) : "l"(a), "l"(b)); return d;
}
__device__ __forceinline__ u64 add2(u64 a, u64 b) {
    u64 d; asm("add.rn.f32x2 %0, %1, %2;" : "=l"(d) : "l"(a), "l"(b)); return d;
}

// CNOT ring: pure compile-time index permutation on packed amplitudes.
__device__ __forceinline__ void apply_cnot_ring(u64* __restrict__ psi)
{
    u64 t[16];
    #pragma unroll
    for (int i = 0; i < 16; i++) t[i] = psi[((i >> 3) & 1) ? (i ^ 4) : i];   // CNOT(0,1)
    u64 t2[16];
    #pragma unroll
    for (int i = 0; i < 16; i++) t2[i] = t[((i >> 2) & 1) ? (i ^ 2) : i];    // CNOT(1,2)
    #pragma unroll
    for (int i = 0; i < 16; i++) t[i] = t2[((i >> 1) & 1) ? (i ^ 1) : i];    // CNOT(2,3)
    #pragma unroll
    for (int i = 0; i < 16; i++) psi[i] = t[(i & 1) ? (i ^ 8) : i];          // CNOT(3,0)
}

// Packed RY layer with batch-uniform coefficients.
__device__ __forceinline__ void apply_ry_layer2(u64* __restrict__ psi,
                                                const float* __restrict__ cv,
                                                const float* __restrict__ sv)
{
    #pragma unroll
    for (int q = 0; q < 4; q++) {
        const int m = 1 << (3 - q);
        const float cq = cv[q], sq = sv[q];
        const u64 c2q  = pk(cq,  cq);
        const u64 s2q  = pk(sq,  sq);
        const u64 ns2q = pk(-sq, -sq);
        #pragma unroll
        for (int i = 0; i < 16; i++) {
            if (!(i & m)) {
                u64 a0 = psi[i];
                u64 a1 = psi[i | m];
                psi[i]     = fma2(c2q, a0, mul2(ns2q, a1));  // c*a0 - s*a1
                psi[i | m] = fma2(s2q, a0, mul2(c2q,  a1));  // s*a0 + c*a1
            }
        }
    }
}

// Scalar per-sample tail: Linear(4,6) + softmax into smem slot.
__device__ __forceinline__ void tail(const Params& sp,
                                     float e0, float e1, float e2, float e3,
                                     float* __restrict__ dst)
{
    float ex[6];
    float den = 0.f;
    #pragma unroll
    for (int j = 0; j < 6; j++) {
        float l = sp.b[j];
        l = fmaf(e0, sp.W[j][0], l);
        l = fmaf(e1, sp.W[j][1], l);
        l = fmaf(e2, sp.W[j][2], l);
        l = fmaf(e3, sp.W[j][3], l);
        ex[j] = __expf(l);
        den += ex[j];
    }
    float inv = __fdividef(1.0f, den);
    #pragma unroll
    for (int j = 0; j < 6; j++) dst[j] = ex[j] * inv;
}

__global__ __launch_bounds__(128) void qnn_kernel(const float4* __restrict__ x,
                                                  float* __restrict__ out,
                                                  int B)
{
    __shared__ Params sp;
    __shared__ float obuf[256 * 6];

    {
        constexpr int NW = sizeof(Params) / 4;
        if (threadIdx.x < NW)
            ((float*)&sp)[threadIdx.x] = ((const float*)&g_params)[threadIdx.x];
    }
    __syncthreads();

    const int tid  = threadIdx.x;
    const int base = blockIdx.x * 256;
    const int s0   = base + tid;
    const int s1   = s0 + 128;

    {
        float4 xv0 = (s0 < B) ? x[s0] : make_float4(0.f, 0.f, 0.f, 0.f);
        float4 xv1 = (s1 < B) ? x[s1] : make_float4(0.f, 0.f, 0.f, 0.f);

        // half-angle sincos per sample (layer-0 weights folded in)
        float ca[4], sa[4], cb[4], sb[4];
        __sincosf(0.5f * (xv0.x + sp.w0[0]), &sa[0], &ca[0]);
        __sincosf(0.5f * (xv0.y + sp.w0[1]), &sa[1], &ca[1]);
        __sincosf(0.5f * (xv0.z + sp.w0[2]), &sa[2], &ca[2]);
        __sincosf(0.5f * (xv0.w + sp.w0[3]), &sa[3], &ca[3]);
        __sincosf(0.5f * (xv1.x + sp.w0[0]), &sb[0], &cb[0]);
        __sincosf(0.5f * (xv1.y + sp.w0[1]), &sb[1], &cb[1]);
        __sincosf(0.5f * (xv1.z + sp.w0[2]), &sb[2], &cb[2]);
        __sincosf(0.5f * (xv1.w + sp.w0[3]), &sb[3], &cb[3]);

        // pack the two samples lane-wise
        u64 c2[4], s2v[4];
        #pragma unroll
        for (int i = 0; i < 4; i++) {
            c2[i]  = pk(ca[i], cb[i]);
            s2v[i] = pk(sa[i], sb[i]);
        }

        // product state: psi[b0b1b2b3] = f0(b0) f1(b1) f2(b2) f3(b3)
        u64 u2[4], v2[4];
        u2[0] = mul2(c2[0],  c2[1]);  u2[1] = mul2(c2[0],  s2v[1]);
        u2[2] = mul2(s2v[0], c2[1]);  u2[3] = mul2(s2v[0], s2v[1]);
        v2[0] = mul2(c2[2],  c2[3]);  v2[1] = mul2(c2[2],  s2v[3]);
        v2[2] = mul2(s2v[2], c2[3]);  v2[3] = mul2(s2v[2], s2v[3]);

        u64 psi[16];
        #pragma unroll
        for (int a = 0; a < 4; a++)
            #pragma unroll
            for (int bb = 0; bb < 4; bb++)
                psi[a * 4 + bb] = mul2(u2[a], v2[bb]);

        // circuit: ring, RY(w1), ring, RY(w2)
        apply_cnot_ring(psi);
        apply_ry_layer2(psi, sp.c1, sp.s1);
        apply_cnot_ring(psi);
        apply_ry_layer2(psi, sp.c2, sp.s2);

        // probabilities
        u64 p[16];
        #pragma unroll
        for (int i = 0; i < 16; i++) p[i] = mul2(psi[i], psi[i]);

        // <Z_w> butterfly (packed); sub via fma2(neg1, y, x)
        const u64 neg1 = pk(-1.f, -1.f);
        u64 A[8], D[8];
        #pragma unroll
        for (int j = 0; j < 8; j++) {
            A[j] = add2(p[j], p[j + 8]);
            D[j] = fma2(neg1, p[j + 8], p[j]);
        }
        u64 E0 = add2(add2(add2(D[0], D[1]), add2(D[2], D[3])),
                      add2(add2(D[4], D[5]), add2(D[6], D[7])));
        u64 sA01 = add2(A[0], A[1]), sA23 = add2(A[2], A[3]);
        u64 sA45 = add2(A[4], A[5]), sA67 = add2(A[6], A[7]);
        u64 E1 = fma2(neg1, add2(sA45, sA67), add2(sA01, sA23));
        u64 E2 = fma2(neg1, add2(sA23, sA67), add2(sA01, sA45));
        u64 sE  = add2(add2(A[0], A[2]), add2(A[4], A[6]));
        u64 sO  = add2(add2(A[1], A[3]), add2(A[5], A[7]));
        u64 E3 = fma2(neg1, sO, sE);

        float e0a, e0b, e1a, e1b, e2a, e2b, e3a, e3b;
        upk(E0, e0a, e0b);
        upk(E1, e1a, e1b);
        upk(E2, e2a, e2b);
        upk(E3, e3a, e3b);

        // scalar tails into smem
        tail(sp, e0a, e1a, e2a, e3a, &obuf[tid * 6]);
        tail(sp, e0b, e1b, e2b, e3b, &obuf[(tid + 128) * 6]);
    }
    __syncthreads();

    // coalesced store of the block's (256,6) output slab
    const long long obase = (long long)blockIdx.x * (256 * 6);
    const long long limit = (long long)B * 6;
    #pragma unroll
    for (int k = 0; k < 12; k++) {
        long long idx = obase + k * 128 + tid;
        if (idx < limit) out[idx] = obuf[k * 128 + tid];
    }
}

extern "C" void kernel_launch(void* const* d_in, const int* in_sizes, int n_in,
                              void* d_out, int out_size)
{
    const float* x  = (const float*)d_in[0];   // (B,4)
    const float* qw = (const float*)d_in[1];   // (3,4)
    const float* W  = (const float*)d_in[2];   // (6,4)
    const float* b  = (const float*)d_in[3];   // (6,)
    float* out = (float*)d_out;                // (B,6)

    const int B = in_sizes[0] / 4;

    prep_kernel<<<1, 32>>>(qw, W, b);
    const int blocks = (B + 255) / 256;        // 256 samples per block
    qnn_kernel<<<blocks, 128>>>((const float4*)x, out, B);
}